// round 15
// baseline (speedup 1.0000x reference)
#include <cuda_runtime.h>
#include <cuda_bf16.h>
#include <float.h>
#include <math.h>
#include <stdint.h>

#define NB 8192
#define ND 64
#define KNN 25
#define KQ 192              // hi(64) | a:lo/b:hi (64) | a:hi/b:lo (64)
#define QTILE 128
#define CCHUNK 128
#define NHALF 2
#define HALFN (NB / NHALF)          // 4096
#define NCH (HALFN / CCHUNK)        // 32
#define NLIST 4                     // 2 halves x 2 col-halves

// ---------------- device scratch ----------------
__device__ __nv_bfloat16 g_A[NB * KQ];
__device__ __nv_bfloat16 g_B[NB * KQ];
__device__ float  g_sq[NB];
__device__ float  g_cand_d[NB * NLIST * KNN];
__device__ int    g_cand_i[NB * NLIST * KNN];
__device__ int    g_knn[NB * KNN];
__device__ float  g_tsa[NB];
__device__ double g_acc;

__device__ __forceinline__ float warp_sum(float v) {
    #pragma unroll
    for (int o = 16; o > 0; o >>= 1) v += __shfl_xor_sync(0xffffffffu, v, o);
    return v;
}
__device__ __forceinline__ unsigned long long ffma2(unsigned long long a,
                                                    unsigned long long b,
                                                    unsigned long long c) {
    unsigned long long d;
    asm("fma.rn.f32x2 %0, %1, %2, %3;" : "=l"(d) : "l"(a), "l"(b), "l"(c));
    return d;
}
__device__ __forceinline__ float2 upk(unsigned long long v) {
    float2 f;
    asm("mov.b64 {%0, %1}, %2;" : "=f"(f.x), "=f"(f.y) : "l"(v));
    return f;
}
__device__ __forceinline__ uint32_t smem_u32(const void* p) {
    uint32_t a;
    asm("{ .reg .u64 t; cvta.to.shared.u64 t, %1; cvt.u32.u64 %0, t; }" : "=r"(a) : "l"(p));
    return a;
}
__device__ __forceinline__ void ldsm_x4(uint32_t& r0, uint32_t& r1, uint32_t& r2, uint32_t& r3,
                                        uint32_t addr) {
    asm volatile("ldmatrix.sync.aligned.m8n8.x4.shared.b16 {%0,%1,%2,%3}, [%4];"
                 : "=r"(r0), "=r"(r1), "=r"(r2), "=r"(r3) : "r"(addr));
}
__device__ __forceinline__ void mma16816(float* d, uint32_t a0, uint32_t a1, uint32_t a2,
                                         uint32_t a3, uint32_t b0, uint32_t b1) {
    asm volatile(
        "mma.sync.aligned.m16n8k16.row.col.f32.bf16.bf16.f32 "
        "{%0,%1,%2,%3}, {%4,%5,%6,%7}, {%8,%9}, {%0,%1,%2,%3};"
        : "+f"(d[0]), "+f"(d[1]), "+f"(d[2]), "+f"(d[3])
        : "r"(a0), "r"(a1), "r"(a2), "r"(a3), "r"(b0), "r"(b1));
}
__device__ __forceinline__ void cp_async16(uint32_t saddr, const void* g) {
    asm volatile("cp.async.cg.shared.global [%0], [%1], 16;" :: "r"(saddr), "l"(g));
}
#define CP_COMMIT() asm volatile("cp.async.commit_group;" ::: "memory")
#define CP_WAIT0()  asm volatile("cp.async.wait_group 0;" ::: "memory")

// dynamic smem layout (bytes)
#define SM_A    0
#define SM_B0   49152
#define SM_B1   98304
#define SM_D    147456                      // 128 x 133 fp32 = 68096
#define DPAD    133
#define SM_SQ0  (SM_D + 128 * DPAD * 4)
#define SM_SQ1  (SM_SQ0 + 512)
#define DSM_SZ  (SM_SQ1 + 512)

// ---------------- init / recon / sq ----------------
__global__ void init_kernel() { g_acc = 0.0; }

__global__ void recon_kernel(const float4* __restrict__ o, const float4* __restrict__ t) {
    float acc = 0.f;
    const int n4 = (NB * ND) / 4;
    for (int i = blockIdx.x * blockDim.x + threadIdx.x; i < n4; i += gridDim.x * blockDim.x) {
        float4 a = o[i], b = t[i];
        float dx = a.x - b.x, dy = a.y - b.y, dz = a.z - b.z, dw = a.w - b.w;
        acc += dx * dx + dy * dy + dz * dz + dw * dw;
    }
    acc = warp_sum(acc);
    __shared__ float sh[8];
    int lane = threadIdx.x & 31, wid = threadIdx.x >> 5;
    if (lane == 0) sh[wid] = acc;
    __syncthreads();
    if (wid == 0) {
        float v = (lane < 8) ? sh[lane] : 0.f;
        v = warp_sum(v);
        if (lane == 0) atomicAdd(&g_acc, (double)v);
    }
}

__global__ void sq_kernel(const float* __restrict__ raw) {
    int r = blockIdx.x * 8 + (threadIdx.x >> 5);
    int lane = threadIdx.x & 31;
    float a = raw[r * ND + lane];
    float b = raw[r * ND + 32 + lane];
    float s = warp_sum(a * a + b * b);
    if (lane == 0) g_sq[r] = s;
}

// ---------------- hi/lo bf16 split:  A=[hi,lo,hi]  B=[hi,hi,lo] ----------------
__global__ void conv_kernel(const float* __restrict__ raw) {
    int i = blockIdx.x * 256 + threadIdx.x;       // pair index: 8192*32
    int row = i >> 5, dp = i & 31;
    float2 x = *(const float2*)(raw + (size_t)row * ND + 2 * dp);
    __nv_bfloat16 h0 = __float2bfloat16(x.x);
    __nv_bfloat16 h1 = __float2bfloat16(x.y);
    __nv_bfloat16 l0 = __float2bfloat16(x.x - __bfloat162float(h0));
    __nv_bfloat16 l1 = __float2bfloat16(x.y - __bfloat162float(h1));
    __nv_bfloat162 hh; hh.x = h0; hh.y = h1;
    __nv_bfloat162 ll; ll.x = l0; ll.y = l1;
    __nv_bfloat162* Ar = (__nv_bfloat162*)(g_A + (size_t)row * KQ);
    __nv_bfloat162* Br = (__nv_bfloat162*)(g_B + (size_t)row * KQ);
    Ar[dp] = hh; Ar[32 + dp] = ll; Ar[64 + dp] = hh;
    Br[dp] = hh; Br[32 + dp] = hh; Br[64 + dp] = ll;
}

// stage 128 rows x 192 bf16 into 3 SW128 subtiles of [128][64]
__device__ __forceinline__ void stage_tile(char* dsm, int off,
                                           const __nv_bfloat16* __restrict__ src,
                                           int row0, int tid) {
    #pragma unroll
    for (int i = 0; i < 12; ++i) {
        int e = tid + i * 256;            // 0..3071
        int r = e / 24, kc = e - r * 24;  // kc: 8-bf16 col group (0..23)
        float4 v = *(const float4*)(src + (size_t)(row0 + r) * KQ + kc * 8);
        int sub = kc >> 3, c8 = kc & 7;
        uint32_t byte = (uint32_t)(sub * 16384 + r * 128 + ((c8 * 16) ^ ((r & 7) << 4)));
        *(float4*)(dsm + off + byte) = v;
    }
}

// async variant (cp.async.cg, 16B)
__device__ __forceinline__ void stage_tile_async(uint32_t soff,
                                                 const __nv_bfloat16* __restrict__ src,
                                                 int row0, int tid) {
    #pragma unroll
    for (int i = 0; i < 12; ++i) {
        int e = tid + i * 256;
        int r = e / 24, kc = e - r * 24;
        const void* g = src + (size_t)(row0 + r) * KQ + kc * 8;
        int sub = kc >> 3, c8 = kc & 7;
        uint32_t byte = (uint32_t)(sub * 16384 + r * 128 + ((c8 * 16) ^ ((r & 7) << 4)));
        cp_async16(soff + byte, g);
    }
}

// ---------------- tensor-core KNN (HMMA mma.sync, double-buffered B) --------
__global__ void __launch_bounds__(256, 1) knn_mma_kernel() {
    extern __shared__ char dsm[];
    const int tid = threadIdx.x, wid = tid >> 5, lane = tid & 31;
    const int q0 = blockIdx.x * QTILE;
    const int cbase = blockIdx.y * HALFN;
    const uint32_t smem = smem_u32(dsm);
    float* Ds = (float*)(dsm + SM_D);

    stage_tile(dsm, SM_A, g_A, q0, tid);
    stage_tile_async(smem + SM_B0, g_B, cbase, tid);
    if (tid < CCHUNK) *(float*)(dsm + SM_SQ0 + tid * 4) = g_sq[cbase + tid];
    CP_COMMIT();

    // per-lane ldmatrix address components
    const int ar = wid * 16 + (lane & 15);
    const int ac8 = lane >> 4;
    const uint32_t a_rowoff = (uint32_t)(ar * 128);
    const uint32_t a_xm = (uint32_t)((ar & 7) << 4);

    float bd_[KNN]; int bi_[KNN];
    #pragma unroll
    for (int t = 0; t < KNN; ++t) { bd_[t] = FLT_MAX; bi_[t] = -1; }
    float worst = FLT_MAX; int wpos = 0;

    const int selr = tid & 127;
    const int selh = tid >> 7;
    const int q = q0 + selr;

    CP_WAIT0();
    __syncthreads();

    for (int ch = 0; ch < NCH; ++ch) {
        const int buf = ch & 1;
        const uint32_t boff = buf ? SM_B1 : SM_B0;

        // prefetch next chunk (async, overlaps mma + select)
        if (ch + 1 < NCH) {
            stage_tile_async(smem + (buf ? SM_B0 : SM_B1), g_B, cbase + (ch + 1) * CCHUNK, tid);
            if (tid < CCHUNK)
                *(float*)(dsm + (buf ? SM_SQ0 : SM_SQ1) + tid * 4) = g_sq[cbase + (ch + 1) * CCHUNK + tid];
        }
        CP_COMMIT();

        float acc[16][4];
        #pragma unroll
        for (int n = 0; n < 16; ++n)
            #pragma unroll
            for (int u = 0; u < 4; ++u) acc[n][u] = 0.f;

        #pragma unroll 1
        for (int kt = 0; kt < 12; ++kt) {
            const int sub = kt >> 2;
            const uint32_t kb = (uint32_t)((kt & 3) * 32);
            uint32_t a0, a1, a2, a3;
            ldsm_x4(a0, a1, a2, a3,
                    smem + SM_A + sub * 16384 + a_rowoff + (((kb + ac8 * 16)) ^ a_xm));
            #pragma unroll
            for (int p = 0; p < 8; ++p) {
                const int br = p * 16 + (lane & 7) + ((lane >> 4) << 3);
                const uint32_t bc16 = (uint32_t)(((lane >> 3) & 1) * 16);
                uint32_t b0, b1, b2, b3;
                ldsm_x4(b0, b1, b2, b3,
                        smem + boff + sub * 16384 + br * 128 + ((kb + bc16) ^ ((uint32_t)((br & 7) << 4))));
                mma16816(acc[2 * p], a0, a1, a2, a3, b0, b1);
                mma16816(acc[2 * p + 1], a0, a1, a2, a3, b2, b3);
            }
        }

        // D fragments -> smem (DPAD=133 odd: SCALAR stores only — float2 at
        // odd row base would be 4B-aligned-only and fault on STS.64)
        {
            const int gr = wid * 16 + (lane >> 2);
            const int cb = (lane & 3) * 2;
            float* r0 = Ds + gr * DPAD;
            float* r1 = Ds + (gr + 8) * DPAD;
            #pragma unroll
            for (int n = 0; n < 16; ++n) {
                int c = n * 8 + cb;
                r0[c]     = acc[n][0];
                r0[c + 1] = acc[n][1];
                r1[c]     = acc[n][2];
                r1[c + 1] = acc[n][3];
            }
        }
        CP_WAIT0();
        __syncthreads();

        // selection: thread owns (row selr, 64-col half selh)
        const float* sqf = (const float*)(dsm + (buf ? SM_SQ1 : SM_SQ0));
        const int j0 = cbase + ch * CCHUNK + selh * 64;
        const float* drow = Ds + selr * DPAD + selh * 64;
        #pragma unroll 4
        for (int c = 0; c < 64; ++c) {
            float v = fmaf(-2.f, drow[c], sqf[selh * 64 + c]);
            int j = j0 + c;
            if (v < worst && j != q) {
                bd_[wpos] = v; bi_[wpos] = j;
                worst = bd_[0]; wpos = 0;
                #pragma unroll
                for (int u = 1; u < KNN; ++u) {
                    float bu = bd_[u];
                    if (bu > worst) { worst = bu; wpos = u; }
                }
            }
        }
        __syncthreads();     // select done before next D write / B reuse
    }

    int base = q * (NLIST * KNN) + blockIdx.y * (2 * KNN) + selh * KNN;
    #pragma unroll
    for (int t = 0; t < KNN; ++t) { g_cand_d[base + t] = bd_[t]; g_cand_i[base + t] = bi_[t]; }
}

// ---------------- merge 4 lists of 25 -> top-25 ----------------
__global__ void merge_kernel() {
    const int lane = threadIdx.x & 31;
    const int q = blockIdx.x * 8 + (threadIdx.x >> 5);
    const int NE = NLIST * KNN;      // 100
    float d[4]; int id[4];
    int base = q * NE;
    #pragma unroll
    for (int t = 0; t < 4; ++t) {
        int j = lane + 32 * t;
        if (j < NE) { d[t] = g_cand_d[base + j]; id[t] = g_cand_i[base + j]; }
        else { d[t] = FLT_MAX; id[t] = -1; }
    }
    for (int r = 0; r < KNN; ++r) {
        float bv = d[0]; int bp = 0;
        #pragma unroll
        for (int t = 1; t < 4; ++t) if (d[t] < bv) { bv = d[t]; bp = t; }
        float rv = bv; int rl = lane;
        #pragma unroll
        for (int o = 16; o > 0; o >>= 1) {
            float ov = __shfl_xor_sync(0xffffffffu, rv, o);
            int ol = __shfl_xor_sync(0xffffffffu, rl, o);
            if (ov < rv || (ov == rv && ol < rl)) { rv = ov; rl = ol; }
        }
        if (lane == rl) { g_knn[q * KNN + r] = id[bp]; d[bp] = FLT_MAX; }
    }
}

// ---------------- TSA (unchanged) ----------------
#define TSA_WPB 4
#define WREG 5504
__global__ void __launch_bounds__(128, 2) tsa_kernel(const float* __restrict__ latent,
                                                     const float* __restrict__ raw) {
    extern __shared__ float dsmf[];
    __shared__ int nbs[TSA_WPB][28];

    const int w = threadIdx.x >> 5, lane = threadIdx.x & 31;
    const int s = blockIdx.x * TSA_WPB + w;
    float* R  = dsmf + w * WREG;
    float* Zr = R;
    float* Xr_s = R + 1728;
    float* Gs = R + 3456;
    float* Gxs = Gs + 675;
    float* Ms  = Gs + 1350;

    if (lane < KNN) nbs[w][lane] = g_knn[s * KNN + lane];
    __syncwarp();

    for (int t = lane; t < KNN * (ND / 4); t += 32) {
        int k = t >> 4, d4 = (t & 15) << 2;
        int nb = nbs[w][k];
        *(float4*)(Zr + k * 68 + d4)   = *(const float4*)(latent + (size_t)nb * ND + d4);
        *(float4*)(Xr_s + k * 68 + d4) = *(const float4*)(raw    + (size_t)nb * ND + d4);
    }
    __syncwarp();

    #pragma unroll 1
    for (int e = lane; e < KNN * KNN; e += 32) {
        int j = e / KNN, k = e - j * KNN;
        const ulonglong2* zj = (const ulonglong2*)(Zr + j * 68);
        const ulonglong2* zk = (const ulonglong2*)(Zr + k * 68);
        const ulonglong2* xj = (const ulonglong2*)(Xr_s + j * 68);
        const ulonglong2* xk = (const ulonglong2*)(Xr_s + k * 68);
        unsigned long long gza = 0ull, gzb = 0ull, gxa = 0ull, gxb = 0ull, ma = 0ull, mb = 0ull;
        #pragma unroll
        for (int t = 0; t < ND / 4; ++t) {
            ulonglong2 a = zj[t], b = zk[t], c = xj[t], dd = xk[t];
            gza = ffma2(a.x, b.x, gza);  gzb = ffma2(a.y, b.y, gzb);
            gxa = ffma2(c.x, dd.x, gxa); gxb = ffma2(c.y, dd.y, gxb);
            ma  = ffma2(a.x, dd.x, ma);  mb  = ffma2(a.y, dd.y, mb);
        }
        float2 z0 = upk(gza), z1 = upk(gzb), x0 = upk(gxa), x1 = upk(gxb), m0 = upk(ma), m1 = upk(mb);
        Gs[j * 27 + k]  = (z0.x + z0.y) + (z1.x + z1.y);
        Gxs[j * 27 + k] = (x0.x + x0.y) + (x1.x + x1.y);
        Ms[j * 27 + k]  = (m0.x + m0.y) + (m1.x + m1.y);
    }
    __syncwarp();

    float Gr[KNN], Xr[KNN], Mr[KNN];
    #pragma unroll
    for (int k = 0; k < KNN; ++k) {
        Gr[k] = (lane < KNN) ? Gs[lane * 27 + k]  : 0.f;
        Xr[k] = (lane < KNN) ? Gxs[lane * 27 + k] : 0.f;
        Mr[k] = (lane < KNN) ? Ms[lane * 27 + k]  : 0.f;
    }

    float a, b;
    {
        unsigned h = (unsigned)lane * 2654435761u;
        float v0 = (lane < KNN) ? ((float)((h >> 16) & 1023) * (1.f / 1024.f) - 0.5f) : 0.f;
        float m = warp_sum(v0) * (1.f / KNN);
        a = (lane < KNN) ? v0 - m : 0.f;
        b = a;
    }
    for (int it = 0; it < 40; ++it) {
        float ya = 0.f, yb = 0.f;
        #pragma unroll
        for (int k = 0; k < KNN; ++k) {
            float as = __shfl_sync(0xffffffffu, a, k);
            float bs = __shfl_sync(0xffffffffu, b, k);
            ya = fmaf(Gr[k], as, ya);
            yb = fmaf(Xr[k], bs, yb);
        }
        float ma = warp_sum(ya) * (1.f / KNN);
        float mb2 = warp_sum(yb) * (1.f / KNN);
        ya = (lane < KNN) ? ya - ma : 0.f;
        yb = (lane < KNN) ? yb - mb2 : 0.f;
        if ((it & 3) == 3) {
            float na = warp_sum(ya * ya);
            float nb2 = warp_sum(yb * yb);
            ya *= rsqrtf(na + 1e-30f);
            yb *= rsqrtf(nb2 + 1e-30f);
        }
        a = ya; b = yb;
    }

    float ya = 0.f, yb = 0.f, sm = 0.f;
    #pragma unroll
    for (int k = 0; k < KNN; ++k) {
        float as = __shfl_sync(0xffffffffu, a, k);
        float bs = __shfl_sync(0xffffffffu, b, k);
        ya = fmaf(Gr[k], as, ya);
        yb = fmaf(Xr[k], bs, yb);
        sm = fmaf(Mr[k], bs, sm);
    }
    float qz = warp_sum(a * ya);
    float qx = warp_sum(b * yb);
    float sab = warp_sum(a * sm);

    float denom = qz * qx;
    float cos2 = (denom > 1e-20f) ? (sab * sab) / denom : 0.f;
    if (lane == 0) g_tsa[s] = 2.f - 2.f * cos2;
}

// ---------------- finalize ----------------
__global__ void finalize_kernel(float* __restrict__ out) {
    __shared__ float sh[32];
    float s = 0.f;
    for (int i = threadIdx.x; i < NB; i += blockDim.x) s += g_tsa[i];
    s = warp_sum(s);
    int lane = threadIdx.x & 31, wid = threadIdx.x >> 5;
    if (lane == 0) sh[wid] = s;
    __syncthreads();
    if (wid == 0) {
        float v = (lane < (int)(blockDim.x >> 5)) ? sh[lane] : 0.f;
        v = warp_sum(v);
        if (lane == 0) {
            double recon = g_acc / (double)(NB * ND);
            out[0] = (float)(recon + 0.1 * ((double)v / (double)NB));
        }
    }
}

extern "C" void kernel_launch(void* const* d_in, const int* in_sizes, int n_in,
                              void* d_out, int out_size) {
    const float* outputs = (const float*)d_in[0];
    const float* targets = (const float*)d_in[1];
    const float* latent  = (const float*)d_in[2];
    const float* raw     = (const float*)d_in[3];
    float* out = (float*)d_out;

    cudaFuncSetAttribute(knn_mma_kernel, cudaFuncAttributeMaxDynamicSharedMemorySize, DSM_SZ);
    cudaFuncSetAttribute(tsa_kernel, cudaFuncAttributeMaxDynamicSharedMemorySize,
                         TSA_WPB * WREG * (int)sizeof(float));

    // knn_mma at launch position 4 -> it gets the ncu profile slot
    init_kernel<<<1, 1>>>();
    conv_kernel<<<NB * 32 / 256, 256>>>(raw);
    sq_kernel<<<NB / 8, 256>>>(raw);
    knn_mma_kernel<<<dim3(NB / QTILE, NHALF), 256, DSM_SZ>>>();
    merge_kernel<<<NB / 8, 256>>>();
    recon_kernel<<<256, 256>>>((const float4*)outputs, (const float4*)targets);
    tsa_kernel<<<NB / TSA_WPB, 128, TSA_WPB * WREG * (int)sizeof(float)>>>(latent, raw);
    finalize_kernel<<<1, 1024>>>(out);
}

// round 16
// speedup vs baseline: 1.2882x; 1.2882x over previous
#include <cuda_runtime.h>
#include <cuda_bf16.h>
#include <float.h>
#include <math.h>
#include <stdint.h>

#define NB 8192
#define ND 64
#define KNN 25
#define QTILE 128
#define CCHUNK 128
#define NQ 4
#define QUARTN (NB / NQ)            // 2048
#define NCH (QUARTN / CCHUNK)       // 16
#define NLIST 8                     // 4 quarters x 2 col-half threads

// ---------------- device scratch ----------------
__device__ __nv_bfloat16 g_X[NB * ND];
__device__ float    g_sq[NB];
__device__ uint32_t g_cand_k[NB * NLIST * KNN];
__device__ int      g_knn[NB * KNN];
__device__ float    g_tsa[NB];
__device__ double   g_acc;

__device__ __forceinline__ float warp_sum(float v) {
    #pragma unroll
    for (int o = 16; o > 0; o >>= 1) v += __shfl_xor_sync(0xffffffffu, v, o);
    return v;
}
__device__ __forceinline__ unsigned long long ffma2(unsigned long long a,
                                                    unsigned long long b,
                                                    unsigned long long c) {
    unsigned long long d;
    asm("fma.rn.f32x2 %0, %1, %2, %3;" : "=l"(d) : "l"(a), "l"(b), "l"(c));
    return d;
}
__device__ __forceinline__ float2 upk(unsigned long long v) {
    float2 f;
    asm("mov.b64 {%0, %1}, %2;" : "=f"(f.x), "=f"(f.y) : "l"(v));
    return f;
}
__device__ __forceinline__ uint32_t smem_u32(const void* p) {
    uint32_t a;
    asm("{ .reg .u64 t; cvta.to.shared.u64 t, %1; cvt.u32.u64 %0, t; }" : "=r"(a) : "l"(p));
    return a;
}
__device__ __forceinline__ void ldsm_x4(uint32_t& r0, uint32_t& r1, uint32_t& r2, uint32_t& r3,
                                        uint32_t addr) {
    asm volatile("ldmatrix.sync.aligned.m8n8.x4.shared.b16 {%0,%1,%2,%3}, [%4];"
                 : "=r"(r0), "=r"(r1), "=r"(r2), "=r"(r3) : "r"(addr));
}
__device__ __forceinline__ void mma16816(float* d, uint32_t a0, uint32_t a1, uint32_t a2,
                                         uint32_t a3, uint32_t b0, uint32_t b1) {
    asm volatile(
        "mma.sync.aligned.m16n8k16.row.col.f32.bf16.bf16.f32 "
        "{%0,%1,%2,%3}, {%4,%5,%6,%7}, {%8,%9}, {%0,%1,%2,%3};"
        : "+f"(d[0]), "+f"(d[1]), "+f"(d[2]), "+f"(d[3])
        : "r"(a0), "r"(a1), "r"(a2), "r"(a3), "r"(b0), "r"(b1));
}
__device__ __forceinline__ void cp_async16(uint32_t saddr, const void* g) {
    asm volatile("cp.async.cg.shared.global [%0], [%1], 16;" :: "r"(saddr), "l"(g));
}
#define CP_COMMIT() asm volatile("cp.async.commit_group;" ::: "memory")
#define CP_WAIT0()  asm volatile("cp.async.wait_group 0;" ::: "memory")

// sortable key: high bits = order-preserving float, low 11 bits = idx in quarter
__device__ __forceinline__ uint32_t pack_key(float v, uint32_t idx11) {
    uint32_t b = __float_as_uint(v);
    b ^= (uint32_t)(((int)b) >> 31) | 0x80000000u;
    return (b & 0xFFFFF800u) | idx11;
}

// dynamic smem layout (bytes): A 16K | B0 16K | B1 16K | D 128x68 f32 | sq0 | sq1
#define SM_A    0
#define SM_B0   16384
#define SM_B1   32768
#define SM_D    49152
#define DPAD    68
#define SM_SQ0  (SM_D + 128 * DPAD * 4)     // 83968
#define SM_SQ1  (SM_SQ0 + 512)
#define DSM_SZ  (SM_SQ1 + 512)              // 84992 (~83KB) -> 2 CTAs/SM

// ---------------- init / recon / sq / conv ----------------
__global__ void init_kernel() { g_acc = 0.0; }

__global__ void recon_kernel(const float4* __restrict__ o, const float4* __restrict__ t) {
    float acc = 0.f;
    const int n4 = (NB * ND) / 4;
    for (int i = blockIdx.x * blockDim.x + threadIdx.x; i < n4; i += gridDim.x * blockDim.x) {
        float4 a = o[i], b = t[i];
        float dx = a.x - b.x, dy = a.y - b.y, dz = a.z - b.z, dw = a.w - b.w;
        acc += dx * dx + dy * dy + dz * dz + dw * dw;
    }
    acc = warp_sum(acc);
    __shared__ float sh[8];
    int lane = threadIdx.x & 31, wid = threadIdx.x >> 5;
    if (lane == 0) sh[wid] = acc;
    __syncthreads();
    if (wid == 0) {
        float v = (lane < 8) ? sh[lane] : 0.f;
        v = warp_sum(v);
        if (lane == 0) atomicAdd(&g_acc, (double)v);
    }
}

__global__ void sq_kernel(const float* __restrict__ raw) {
    int r = blockIdx.x * 8 + (threadIdx.x >> 5);
    int lane = threadIdx.x & 31;
    float a = raw[r * ND + lane];
    float b = raw[r * ND + 32 + lane];
    float s = warp_sum(a * a + b * b);
    if (lane == 0) g_sq[r] = s;
}

__global__ void conv_kernel(const float* __restrict__ raw) {
    int i = blockIdx.x * 256 + threadIdx.x;    // bf16x2 index: 8192*32
    float2 x = *(const float2*)(raw + 2 * (size_t)i);
    __nv_bfloat162 h;
    h.x = __float2bfloat16(x.x);
    h.y = __float2bfloat16(x.y);
    ((__nv_bfloat162*)g_X)[i] = h;
}

// stage 128 rows x 64 bf16 (one SW128 subtile, 16KB)
__device__ __forceinline__ void stage_tile(char* dsm, int off,
                                           const __nv_bfloat16* __restrict__ src,
                                           int row0, int tid) {
    #pragma unroll
    for (int i = 0; i < 4; ++i) {
        int e = tid + i * 256;            // 0..1023
        int r = e >> 3, c8 = e & 7;
        float4 v = *(const float4*)(src + (size_t)(row0 + r) * ND + c8 * 8);
        uint32_t byte = (uint32_t)(r * 128 + ((c8 * 16) ^ ((r & 7) << 4)));
        *(float4*)(dsm + off + byte) = v;
    }
}
__device__ __forceinline__ void stage_tile_async(uint32_t soff,
                                                 const __nv_bfloat16* __restrict__ src,
                                                 int row0, int tid) {
    #pragma unroll
    for (int i = 0; i < 4; ++i) {
        int e = tid + i * 256;
        int r = e >> 3, c8 = e & 7;
        const void* g = src + (size_t)(row0 + r) * ND + c8 * 8;
        uint32_t byte = (uint32_t)(r * 128 + ((c8 * 16) ^ ((r & 7) << 4)));
        cp_async16(soff + byte, g);
    }
}

// ---------------- tensor-core KNN: K=64 bf16, 2 CTAs/SM, two-stage select ----
__global__ void __launch_bounds__(256, 2) knn_mma_kernel() {
    extern __shared__ char dsm[];
    const int tid = threadIdx.x, wid = tid >> 5, lane = tid & 31;
    const int q0 = blockIdx.x * QTILE;
    const int cbase = blockIdx.y * QUARTN;
    const uint32_t smem = smem_u32(dsm);
    float* Ds = (float*)(dsm + SM_D);

    stage_tile(dsm, SM_A, g_X, q0, tid);
    stage_tile_async(smem + SM_B0, g_X, cbase, tid);
    if (tid < CCHUNK) *(float*)(dsm + SM_SQ0 + tid * 4) = g_sq[cbase + tid];
    CP_COMMIT();

    const int ar = wid * 16 + (lane & 15);
    const int ac8 = lane >> 4;
    const uint32_t a_rowoff = (uint32_t)(ar * 128);
    const uint32_t a_xm = (uint32_t)((ar & 7) << 4);

    uint32_t keys[KNN];
    #pragma unroll
    for (int t = 0; t < KNN; ++t) keys[t] = 0xFFFFFFFFu;
    uint32_t worst = 0xFFFFFFFFu; int wpos = 0;

    const int selr = tid & 127;        // query row
    const int h = tid >> 7;            // 32-col quarter within each 64-col stage
    const int q = q0 + selr;

    CP_WAIT0();
    __syncthreads();

    for (int ch = 0; ch < NCH; ++ch) {
        const int buf = ch & 1;
        const uint32_t boff = buf ? SM_B1 : SM_B0;

        if (ch + 1 < NCH) {
            stage_tile_async(smem + (buf ? SM_B0 : SM_B1), g_X, cbase + (ch + 1) * CCHUNK, tid);
            if (tid < CCHUNK)
                *(float*)(dsm + (buf ? SM_SQ0 : SM_SQ1) + tid * 4) = g_sq[cbase + (ch + 1) * CCHUNK + tid];
        }
        CP_COMMIT();

        float acc[16][4];
        #pragma unroll
        for (int n = 0; n < 16; ++n)
            #pragma unroll
            for (int u = 0; u < 4; ++u) acc[n][u] = 0.f;

        #pragma unroll
        for (int kt = 0; kt < 4; ++kt) {
            const uint32_t kb = (uint32_t)(kt * 32);
            uint32_t a0, a1, a2, a3;
            ldsm_x4(a0, a1, a2, a3,
                    smem + SM_A + a_rowoff + ((kb + ac8 * 16) ^ a_xm));
            #pragma unroll
            for (int p = 0; p < 8; ++p) {
                const int br = p * 16 + (lane & 7) + ((lane >> 4) << 3);
                const uint32_t bc16 = (uint32_t)(((lane >> 3) & 1) * 16);
                uint32_t b0, b1, b2, b3;
                ldsm_x4(b0, b1, b2, b3,
                        smem + boff + br * 128 + ((kb + bc16) ^ ((uint32_t)((br & 7) << 4))));
                mma16816(acc[2 * p], a0, a1, a2, a3, b0, b1);
                mma16816(acc[2 * p + 1], a0, a1, a2, a3, b2, b3);
            }
        }

        const float* sqf = (const float*)(dsm + (buf ? SM_SQ1 : SM_SQ0));
        const int gr = wid * 16 + (lane >> 2);
        const int cb = (lane & 3) * 2;

        #pragma unroll
        for (int s = 0; s < 2; ++s) {
            // stage s: store cols [s*64, s*64+64) of D
            {
                float* r0 = Ds + gr * DPAD;
                float* r1 = Ds + (gr + 8) * DPAD;
                #pragma unroll
                for (int n2 = 0; n2 < 8; ++n2) {
                    int n = s * 8 + n2;
                    int c = n2 * 8 + cb;
                    *(float2*)(r0 + c) = make_float2(acc[n][0], acc[n][1]);
                    *(float2*)(r1 + c) = make_float2(acc[n][2], acc[n][3]);
                }
            }
            __syncthreads();
            // select over this thread's 32 cols of stage s
            {
                const int jc0 = s * 64 + h * 32;
                const float4* dr = (const float4*)(Ds + selr * DPAD + h * 32);
                const int idx0 = ch * CCHUNK + jc0;
                #pragma unroll
                for (int c4 = 0; c4 < 8; ++c4) {
                    float4 dv = dr[c4];
                    float vv[4] = {dv.x, dv.y, dv.z, dv.w};
                    #pragma unroll
                    for (int u = 0; u < 4; ++u) {
                        int idx = idx0 + c4 * 4 + u;
                        float v = fmaf(-2.f, vv[u], sqf[jc0 + c4 * 4 + u]);
                        uint32_t key = pack_key(v, (uint32_t)idx);
                        if (key < worst && (cbase + idx) != q) {
                            keys[wpos] = key;
                            worst = keys[0]; wpos = 0;
                            #pragma unroll
                            for (int t = 1; t < KNN; ++t) {
                                uint32_t kv = keys[t];
                                if (kv > worst) { worst = kv; wpos = t; }
                            }
                        }
                    }
                }
            }
            __syncthreads();   // select done before next stage overwrites Ds
        }
        CP_WAIT0();
        __syncthreads();       // next chunk's B/sq resident; Ds free
    }

    int base = q * (NLIST * KNN) + blockIdx.y * (2 * KNN) + h * KNN;
    #pragma unroll
    for (int t = 0; t < KNN; ++t) g_cand_k[base + t] = keys[t];
}

// ---------------- merge 8 lists of 25 -> top-25 ----------------
__global__ void merge_kernel() {
    const int lane = threadIdx.x & 31;
    const int q = blockIdx.x * 8 + (threadIdx.x >> 5);
    const int NE = NLIST * KNN;      // 200
    uint32_t d[7];
    int base = q * NE;
    #pragma unroll
    for (int t = 0; t < 7; ++t) {
        int j = lane + 32 * t;
        d[t] = (j < NE) ? g_cand_k[base + j] : 0xFFFFFFFFu;
    }
    for (int r = 0; r < KNN; ++r) {
        uint32_t bv = d[0]; int bp = 0;
        #pragma unroll
        for (int t = 1; t < 7; ++t) if (d[t] < bv) { bv = d[t]; bp = t; }
        uint32_t rv = bv; int rl = lane;
        #pragma unroll
        for (int o = 16; o > 0; o >>= 1) {
            uint32_t ov = __shfl_xor_sync(0xffffffffu, rv, o);
            int ol = __shfl_xor_sync(0xffffffffu, rl, o);
            if (ov < rv || (ov == rv && ol < rl)) { rv = ov; rl = ol; }
        }
        if (lane == rl) {
            int pos = lane + 32 * bp;            // flat position 0..199
            int quarter = pos / (2 * KNN);
            g_knn[q * KNN + r] = quarter * QUARTN + (int)(d[bp] & 0x7FFu);
            d[bp] = 0xFFFFFFFFu;
        }
    }
}

// ---------------- TSA (unchanged) ----------------
#define TSA_WPB 4
#define WREG 5504
__global__ void __launch_bounds__(128, 2) tsa_kernel(const float* __restrict__ latent,
                                                     const float* __restrict__ raw) {
    extern __shared__ float dsmf[];
    __shared__ int nbs[TSA_WPB][28];

    const int w = threadIdx.x >> 5, lane = threadIdx.x & 31;
    const int s = blockIdx.x * TSA_WPB + w;
    float* R  = dsmf + w * WREG;
    float* Zr = R;
    float* Xr_s = R + 1728;
    float* Gs = R + 3456;
    float* Gxs = Gs + 675;
    float* Ms  = Gs + 1350;

    if (lane < KNN) nbs[w][lane] = g_knn[s * KNN + lane];
    __syncwarp();

    for (int t = lane; t < KNN * (ND / 4); t += 32) {
        int k = t >> 4, d4 = (t & 15) << 2;
        int nb = nbs[w][k];
        *(float4*)(Zr + k * 68 + d4)   = *(const float4*)(latent + (size_t)nb * ND + d4);
        *(float4*)(Xr_s + k * 68 + d4) = *(const float4*)(raw    + (size_t)nb * ND + d4);
    }
    __syncwarp();

    #pragma unroll 1
    for (int e = lane; e < KNN * KNN; e += 32) {
        int j = e / KNN, k = e - j * KNN;
        const ulonglong2* zj = (const ulonglong2*)(Zr + j * 68);
        const ulonglong2* zk = (const ulonglong2*)(Zr + k * 68);
        const ulonglong2* xj = (const ulonglong2*)(Xr_s + j * 68);
        const ulonglong2* xk = (const ulonglong2*)(Xr_s + k * 68);
        unsigned long long gza = 0ull, gzb = 0ull, gxa = 0ull, gxb = 0ull, ma = 0ull, mb = 0ull;
        #pragma unroll
        for (int t = 0; t < ND / 4; ++t) {
            ulonglong2 a = zj[t], b = zk[t], c = xj[t], dd = xk[t];
            gza = ffma2(a.x, b.x, gza);  gzb = ffma2(a.y, b.y, gzb);
            gxa = ffma2(c.x, dd.x, gxa); gxb = ffma2(c.y, dd.y, gxb);
            ma  = ffma2(a.x, dd.x, ma);  mb  = ffma2(a.y, dd.y, mb);
        }
        float2 z0 = upk(gza), z1 = upk(gzb), x0 = upk(gxa), x1 = upk(gxb), m0 = upk(ma), m1 = upk(mb);
        Gs[j * 27 + k]  = (z0.x + z0.y) + (z1.x + z1.y);
        Gxs[j * 27 + k] = (x0.x + x0.y) + (x1.x + x1.y);
        Ms[j * 27 + k]  = (m0.x + m0.y) + (m1.x + m1.y);
    }
    __syncwarp();

    float Gr[KNN], Xr[KNN], Mr[KNN];
    #pragma unroll
    for (int k = 0; k < KNN; ++k) {
        Gr[k] = (lane < KNN) ? Gs[lane * 27 + k]  : 0.f;
        Xr[k] = (lane < KNN) ? Gxs[lane * 27 + k] : 0.f;
        Mr[k] = (lane < KNN) ? Ms[lane * 27 + k]  : 0.f;
    }

    float a, b;
    {
        unsigned h = (unsigned)lane * 2654435761u;
        float v0 = (lane < KNN) ? ((float)((h >> 16) & 1023) * (1.f / 1024.f) - 0.5f) : 0.f;
        float m = warp_sum(v0) * (1.f / KNN);
        a = (lane < KNN) ? v0 - m : 0.f;
        b = a;
    }
    for (int it = 0; it < 40; ++it) {
        float ya = 0.f, yb = 0.f;
        #pragma unroll
        for (int k = 0; k < KNN; ++k) {
            float as = __shfl_sync(0xffffffffu, a, k);
            float bs = __shfl_sync(0xffffffffu, b, k);
            ya = fmaf(Gr[k], as, ya);
            yb = fmaf(Xr[k], bs, yb);
        }
        float ma = warp_sum(ya) * (1.f / KNN);
        float mb2 = warp_sum(yb) * (1.f / KNN);
        ya = (lane < KNN) ? ya - ma : 0.f;
        yb = (lane < KNN) ? yb - mb2 : 0.f;
        if ((it & 3) == 3) {
            float na = warp_sum(ya * ya);
            float nb2 = warp_sum(yb * yb);
            ya *= rsqrtf(na + 1e-30f);
            yb *= rsqrtf(nb2 + 1e-30f);
        }
        a = ya; b = yb;
    }

    float ya = 0.f, yb = 0.f, sm = 0.f;
    #pragma unroll
    for (int k = 0; k < KNN; ++k) {
        float as = __shfl_sync(0xffffffffu, a, k);
        float bs = __shfl_sync(0xffffffffu, b, k);
        ya = fmaf(Gr[k], as, ya);
        yb = fmaf(Xr[k], bs, yb);
        sm = fmaf(Mr[k], bs, sm);
    }
    float qz = warp_sum(a * ya);
    float qx = warp_sum(b * yb);
    float sab = warp_sum(a * sm);

    float denom = qz * qx;
    float cos2 = (denom > 1e-20f) ? (sab * sab) / denom : 0.f;
    if (lane == 0) g_tsa[s] = 2.f - 2.f * cos2;
}

// ---------------- finalize ----------------
__global__ void finalize_kernel(float* __restrict__ out) {
    __shared__ float sh[32];
    float s = 0.f;
    for (int i = threadIdx.x; i < NB; i += blockDim.x) s += g_tsa[i];
    s = warp_sum(s);
    int lane = threadIdx.x & 31, wid = threadIdx.x >> 5;
    if (lane == 0) sh[wid] = s;
    __syncthreads();
    if (wid == 0) {
        float v = (lane < (int)(blockDim.x >> 5)) ? sh[lane] : 0.f;
        v = warp_sum(v);
        if (lane == 0) {
            double recon = g_acc / (double)(NB * ND);
            out[0] = (float)(recon + 0.1 * ((double)v / (double)NB));
        }
    }
}

extern "C" void kernel_launch(void* const* d_in, const int* in_sizes, int n_in,
                              void* d_out, int out_size) {
    const float* outputs = (const float*)d_in[0];
    const float* targets = (const float*)d_in[1];
    const float* latent  = (const float*)d_in[2];
    const float* raw     = (const float*)d_in[3];
    float* out = (float*)d_out;

    cudaFuncSetAttribute(knn_mma_kernel, cudaFuncAttributeMaxDynamicSharedMemorySize, DSM_SZ);
    cudaFuncSetAttribute(tsa_kernel, cudaFuncAttributeMaxDynamicSharedMemorySize,
                         TSA_WPB * WREG * (int)sizeof(float));

    // knn_mma at launch position 4 -> ncu profile slot
    init_kernel<<<1, 1>>>();
    conv_kernel<<<NB * 32 / 256, 256>>>(raw);
    sq_kernel<<<NB / 8, 256>>>(raw);
    knn_mma_kernel<<<dim3(NB / QTILE, NQ), 256, DSM_SZ>>>();
    merge_kernel<<<NB / 8, 256>>>();
    recon_kernel<<<256, 256>>>((const float4*)outputs, (const float4*)targets);
    tsa_kernel<<<NB / TSA_WPB, 128, TSA_WPB * WREG * (int)sizeof(float)>>>(latent, raw);
    finalize_kernel<<<1, 1024>>>(out);
}